// round 12
// baseline (speedup 1.0000x reference)
#include <cuda_runtime.h>
#include <cuda_fp16.h>
#include <cstdint>

#define N_NODES 100000
#define N_EDGES 1000000
#define D 64

// Scratch: device globals (no allocs allowed).
__device__ uint4 g_yh[(size_t)N_NODES * 8];    // message MLP output, fp16 (64 halves/row)
__device__ uint4 g_aggh[(size_t)N_NODES * 8];  // scatter-sum accumulator, fp16
__device__ int   g_ei_is64;                    // 1 if edge_index is int64

// ---------------------------------------------------------------------------
// fp16 tensor-core MLP building blocks.
// CTA = 256 threads (8 warps); tile = 128 rows x 64 cols of HALF, pitch 72
// halves (=144B rows: frag bank = (4g+tig)%32 -> conflict-free).
// Warp w owns rows [16w,16w+16) x all 64 cols: 8 mma m16n8k16 tiles, k-loop 4.
// Weights staged TRANSPOSED: wT[c*72 + k] (half), so B-frags are direct
// 32-bit LDS of (k,k+1) pairs per output column.
// mma.m16n8k16 fragments (lane: g=lane>>2, tig=lane&3):
//   A: a0=(g,2tig) a1=(g+8,2tig) a2=(g,2tig+8) a3=(g+8,2tig+8)   [row][k], half2
//   B: b0=(2tig,col) b1=(2tig+8,col)                              [k][col], half2
//   C (f32): c0=(g,2tig) c1=(g,2tig+1) c2=(g+8,2tig) c3=(g+8,2tig+1)
// ---------------------------------------------------------------------------
#define PITCH 72   // halves
#define TROWS 128

// Stage 128x64 f32 gmem slab -> half tile (zero-padded).
__device__ __forceinline__ void stage_tile_f32(__half* xs, const float4* src4,
                                               int n0, int tid) {
#pragma unroll
    for (int it = 0; it < 8; it++) {
        int i = tid + it * 256;                 // float4 index, 2048 total
        int l = i >> 4, kq = i & 15;
        float4 v = make_float4(0.f, 0.f, 0.f, 0.f);
        if (n0 + l < N_NODES) v = src4[i];
        __half2 h01 = __floats2half2_rn(v.x, v.y);
        __half2 h23 = __floats2half2_rn(v.z, v.w);
        uint2 u = make_uint2(*(uint32_t*)&h01, *(uint32_t*)&h23);
        *(uint2*)(xs + l * PITCH + 4 * kq) = u;
    }
}

// Stage 128x64 fp16 slab (8 x uint4 per row) -> half tile, raw copy.
__device__ __forceinline__ void stage_tile_h16(__half* xs, const uint4* src,
                                               int n0, int tid) {
#pragma unroll
    for (int it = 0; it < 4; it++) {
        int i = tid + it * 256;                 // uint4 index, 1024 total
        int l = i >> 3, kq = i & 7;
        uint4 v = make_uint4(0u, 0u, 0u, 0u);
        if (n0 + l < N_NODES) v = src[i];
        *(uint4*)(xs + l * PITCH + 8 * kq) = v;   // 144B pitch: 16B-aligned
    }
}

// Stage 64x64 f32 row-major weights -> transposed half wT[c*72 + k].
__device__ __forceinline__ void stage_wT(__half* wt, const float* __restrict__ w,
                                         int tid) {
    for (int idx = tid; idx < 64 * 64; idx += 256) {
        int k = idx >> 6, c = idx & 63;
        wt[c * PITCH + k] = __float2half_rn(w[idx]);
    }
}

// acc += tile[r0..r0+15][0..64) @ W[0..64)[0..64)   (W given as wT[c][k])
__device__ __forceinline__ void mma_sweep(float acc[8][4], const __half* xs,
                                          const __half* wt, int r0, int g, int tig) {
#pragma unroll
    for (int s = 0; s < 4; s++) {
        const int k0 = 16 * s;
        const __half* xr0 = xs + (r0 + g) * PITCH + k0 + 2 * tig;
        const __half* xr8 = xs + (r0 + 8 + g) * PITCH + k0 + 2 * tig;
        uint32_t a0 = *(const uint32_t*)(xr0);
        uint32_t a1 = *(const uint32_t*)(xr8);
        uint32_t a2 = *(const uint32_t*)(xr0 + 8);
        uint32_t a3 = *(const uint32_t*)(xr8 + 8);
#pragma unroll
        for (int t = 0; t < 8; t++) {
            const __half* wc = wt + (8 * t + g) * PITCH + k0 + 2 * tig;
            uint32_t b0 = *(const uint32_t*)(wc);
            uint32_t b1 = *(const uint32_t*)(wc + 8);
            asm volatile(
                "mma.sync.aligned.m16n8k16.row.col.f32.f16.f16.f32 "
                "{%0,%1,%2,%3}, {%4,%5,%6,%7}, {%8,%9}, {%0,%1,%2,%3};"
                : "+f"(acc[t][0]), "+f"(acc[t][1]), "+f"(acc[t][2]), "+f"(acc[t][3])
                : "r"(a0), "r"(a1), "r"(a2), "r"(a3), "r"(b0), "r"(b1));
        }
    }
}

__device__ __forceinline__ void zero_acc(float acc[8][4]) {
#pragma unroll
    for (int t = 0; t < 8; t++)
#pragma unroll
        for (int p = 0; p < 4; p++) acc[t][p] = 0.f;
}

// relu(acc+bias) -> half tile (warp-own rows), one half2 store per tile-row.
__device__ __forceinline__ void write_h(__half* xs, float acc[8][4],
                                        const float* __restrict__ bias,
                                        int r0, int g, int tig) {
#pragma unroll
    for (int t = 0; t < 8; t++) {
        int c = 8 * t + 2 * tig;
        float b0 = __ldg(bias + c), b1 = __ldg(bias + c + 1);
        __half2 lo = __floats2half2_rn(fmaxf(acc[t][0] + b0, 0.f),
                                       fmaxf(acc[t][1] + b1, 0.f));
        __half2 hi = __floats2half2_rn(fmaxf(acc[t][2] + b0, 0.f),
                                       fmaxf(acc[t][3] + b1, 0.f));
        *(uint32_t*)(xs + (r0 + g) * PITCH + c)     = *(uint32_t*)&lo;
        *(uint32_t*)(xs + (r0 + 8 + g) * PITCH + c) = *(uint32_t*)&hi;
    }
}

// acc+bias -> f32 gmem (guarded), float2 per mma tile-row.
__device__ __forceinline__ void store_out(float* dst, float acc[8][4],
                                          const float* __restrict__ bias,
                                          int n0, int r0, int g, int tig) {
    int nlo = n0 + r0 + g, nhi = nlo + 8;
    bool oklo = nlo < N_NODES, okhi = nhi < N_NODES;
#pragma unroll
    for (int t = 0; t < 8; t++) {
        int c = 8 * t + 2 * tig;
        float b0 = __ldg(bias + c), b1 = __ldg(bias + c + 1);
        if (oklo) {
            float2 v; v.x = acc[t][0] + b0; v.y = acc[t][1] + b1;
            *(float2*)(dst + (size_t)nlo * D + c) = v;
        }
        if (okhi) {
            float2 v; v.x = acc[t][2] + b0; v.y = acc[t][3] + b1;
            *(float2*)(dst + (size_t)nhi * D + c) = v;
        }
    }
}

// acc+bias -> fp16 y buffer (guarded), one half2 (4B) per mma tile-row.
__device__ __forceinline__ void store_out_h(float acc[8][4],
                                            const float* __restrict__ bias,
                                            int n0, int r0, int g, int tig) {
    uint32_t* yh = (uint32_t*)g_yh;   // 32 uints per row
    int nlo = n0 + r0 + g, nhi = nlo + 8;
    bool oklo = nlo < N_NODES, okhi = nhi < N_NODES;
#pragma unroll
    for (int t = 0; t < 8; t++) {
        int c = 8 * t + 2 * tig;
        float b0 = __ldg(bias + c), b1 = __ldg(bias + c + 1);
        if (oklo) {
            __half2 v = __floats2half2_rn(acc[t][0] + b0, acc[t][1] + b1);
            yh[nlo * 32 + (c >> 1)] = *(uint32_t*)&v;
        }
        if (okhi) {
            __half2 v = __floats2half2_rn(acc[t][2] + b0, acc[t][3] + b1);
            yh[nhi * 32 + (c >> 1)] = *(uint32_t*)&v;
        }
    }
}

// ---------------------------------------------------------------------------
// K1: node message MLP  y = relu(x @ W1 + b1) @ W2 + b2   -> fp16 g_yh
// Zeroes this block's g_aggh slice; block 0 detects edge_index dtype.
// Smem ~27.2KB.
// ---------------------------------------------------------------------------
#define K_SMEM_BYTES (TROWS * PITCH * 2 + 64 * PITCH * 2)

__global__ __launch_bounds__(256) void k_msg_mlp(
    const float* __restrict__ x,
    const float* __restrict__ w1, const float* __restrict__ b1,
    const float* __restrict__ w2, const float* __restrict__ b2,
    const int* __restrict__ ei32)
{
    extern __shared__ __half smh[];
    __half* xs = smh;                    // 128*72 half tile (x, then h)
    __half* wt = xs + TROWS * PITCH;     // 64*72 half (W1^T, then W2^T)

    const int tid = threadIdx.x;
    const int n0  = blockIdx.x * TROWS;
    const int lane = tid & 31, warp = tid >> 5;
    const int g = lane >> 2, tig = lane & 3;
    const int r0 = warp * 16;

    // Zero this block's g_aggh slice (fp16: 8 x uint4 per row).
    {
        uint4 z = make_uint4(0u, 0u, 0u, 0u);
#pragma unroll
        for (int it = 0; it < 4; it++) {
            int i = n0 * 8 + tid + it * 256;
            if (i < N_NODES * 8) g_aggh[i] = z;
        }
    }
    if (blockIdx.x == 0 && tid == 0) {
        int is64 = 1;
        for (int i = 0; i < 64; i++)
            if (ei32[2 * i + 1] != 0) { is64 = 0; break; }
        g_ei_is64 = is64;
    }

    stage_wT(wt, w1, tid);
    stage_tile_f32(xs, (const float4*)(x + (size_t)n0 * D), n0, tid);
    __syncthreads();

    float acc[8][4];
    zero_acc(acc);
    mma_sweep(acc, xs, wt, r0, g, tig);    // reads only warp-own tile rows
    __syncwarp();
    write_h(xs, acc, b1, r0, g, tig);      // writes only warp-own tile rows
    __syncthreads();                        // all W1 reads done
    stage_wT(wt, w2, tid);                  // W2^T over W1^T
    __syncthreads();

    zero_acc(acc);
    mma_sweep(acc, xs, wt, r0, g, tig);
    store_out_h(acc, b2, n0, r0, g, tig);
}

// ---------------------------------------------------------------------------
// K2: scatter  agg[col] += y[row]  -- all fp16: 8 threads/edge, each does one
// 16B load + one red.global.add.noftz.v4.f16x2 (8 halves per RED).
// ---------------------------------------------------------------------------
__global__ __launch_bounds__(256) void k_scatter(const void* __restrict__ ei_raw)
{
    int tid = blockIdx.x * blockDim.x + threadIdx.x;
    if (tid >= N_EDGES * 8) return;
    int e = tid >> 3;
    int c = tid & 7;

    int row, col;
    if (g_ei_is64) {
        const long long* ei = (const long long*)ei_raw;
        row = (int)ei[e];
        col = (int)ei[N_EDGES + e];
    } else {
        const int* ei = (const int*)ei_raw;
        row = ei[e];
        col = ei[N_EDGES + e];
    }
    if ((unsigned)row >= N_NODES || (unsigned)col >= N_NODES) return;

    uint4 v = g_yh[(size_t)row * 8 + c];
    uint4* q = g_aggh + (size_t)col * 8 + c;
    asm volatile("red.global.add.noftz.v4.f16x2 [%0], {%1,%2,%3,%4};"
                 :: "l"(q), "r"(v.x), "r"(v.y), "r"(v.z), "r"(v.w)
                 : "memory");
}

// ---------------------------------------------------------------------------
// K3: output MLP  out = relu([x,agg] @ W1 + b1) @ W2 + b2     [N,64]
// Three weight stages through ONE buffer: W1[0:64]^T (x pass),
// W1[64:128]^T (agg pass, fp16 tile loaded raw), W2^T (layer 2).
// ---------------------------------------------------------------------------
__global__ __launch_bounds__(256) void k_out_mlp(
    const float* __restrict__ x,
    const float* __restrict__ w1, const float* __restrict__ b1,
    const float* __restrict__ w2, const float* __restrict__ b2,
    float* __restrict__ out)
{
    extern __shared__ __half smh[];
    __half* xs = smh;                    // 128*72 half tile (x, agg, then h)
    __half* wt = xs + TROWS * PITCH;     // 64*72 half (W1a^T, W1b^T, W2^T)

    const int tid = threadIdx.x;
    const int n0  = blockIdx.x * TROWS;
    const int lane = tid & 31, warp = tid >> 5;
    const int g = lane >> 2, tig = lane & 3;
    const int r0 = warp * 16;

    stage_wT(wt, w1, tid);                           // W1 rows 0..63
    stage_tile_f32(xs, (const float4*)(x + (size_t)n0 * D), n0, tid);
    __syncthreads();

    float acc[8][4];
    zero_acc(acc);
    mma_sweep(acc, xs, wt, r0, g, tig);              // k = 0..63 (x)
    __syncthreads();                                  // x tile + W1a reads done

    stage_tile_h16(xs, g_aggh + (size_t)n0 * 8, n0, tid);
    stage_wT(wt, w1 + 64 * 64, tid);                 // W1 rows 64..127
    __syncthreads();
    mma_sweep(acc, xs, wt, r0, g, tig);              // k = 64..127 (agg)
    __syncwarp();
    write_h(xs, acc, b1, r0, g, tig);
    __syncthreads();                                  // agg tile + W1b reads done
    stage_wT(wt, w2, tid);                           // W2
    __syncthreads();

    zero_acc(acc);
    mma_sweep(acc, xs, wt, r0, g, tig);
    store_out(out, acc, b2, n0, r0, g, tig);
}

// ---------------------------------------------------------------------------
// Launch. Inputs: 0 x, 1 edge_index, 2 batch, 3..6 msg mlp, 7..10 out mlp
// ---------------------------------------------------------------------------
extern "C" void kernel_launch(void* const* d_in, const int* in_sizes, int n_in,
                              void* d_out, int out_size)
{
    const float* x      = (const float*)d_in[0];
    const void*  ei     = d_in[1];
    const float* msg_w1 = (const float*)d_in[3];
    const float* msg_b1 = (const float*)d_in[4];
    const float* msg_w2 = (const float*)d_in[5];
    const float* msg_b2 = (const float*)d_in[6];
    const float* out_w1 = (const float*)d_in[7];
    const float* out_b1 = (const float*)d_in[8];
    const float* out_w2 = (const float*)d_in[9];
    const float* out_b2 = (const float*)d_in[10];
    float*       out    = (float*)d_out;

    cudaFuncSetAttribute(k_msg_mlp, cudaFuncAttributeMaxDynamicSharedMemorySize, K_SMEM_BYTES);
    cudaFuncSetAttribute(k_out_mlp, cudaFuncAttributeMaxDynamicSharedMemorySize, K_SMEM_BYTES);

    const int nodeBlocks = (N_NODES + TROWS - 1) / TROWS;   // 782

    k_msg_mlp<<<nodeBlocks, 256, K_SMEM_BYTES>>>(x, msg_w1, msg_b1, msg_w2, msg_b2,
                                                 (const int*)ei);
    k_scatter<<<(N_EDGES * 8 + 255) / 256, 256>>>(ei);
    k_out_mlp<<<nodeBlocks, 256, K_SMEM_BYTES>>>(x, out_w1, out_b1, out_w2, out_b2, out);
}

// round 13
// speedup vs baseline: 1.1873x; 1.1873x over previous
#include <cuda_runtime.h>
#include <cuda_fp16.h>
#include <cstdint>

#define N_NODES 100000
#define N_EDGES 1000000
#define D 64

// Scratch: device globals (no allocs allowed).
__device__ uint4 g_yh[(size_t)N_NODES * 8];    // message MLP output, fp16 (64 halves/row)
__device__ uint4 g_aggh[(size_t)N_NODES * 8];  // scatter-sum accumulator, fp16
__device__ int   g_ei_is64;                    // 1 if edge_index is int64

// ---------------------------------------------------------------------------
// fp16 tensor-core MLP building blocks.
// CTA = 256 threads (8 warps); tile = 128 rows x 64 cols of HALF, pitch 72.
// Warp w owns rows [16w,16w+16) x all 64 cols: 8 mma m16n8k16 tiles, k-loop 4.
// Weights staged TRANSPOSED wT[c*74 + k] (pitch 74: B-frag banks
// 8t+5g+tig -> conflict-free; staging stores at worst 2-way on 2B).
// mma.m16n8k16 fragments (lane: g=lane>>2, tig=lane&3):
//   A: a0=(g,2tig) a1=(g+8,2tig) a2=(g,2tig+8) a3=(g+8,2tig+8)   [row][k], half2
//   B: b0=(2tig,col) b1=(2tig+8,col)                              [k][col], half2
//   C (f32): c0=(g,2tig) c1=(g,2tig+1) c2=(g+8,2tig) c3=(g+8,2tig+1)
// ---------------------------------------------------------------------------
#define PITCH  72   // tile pitch, halves
#define WPITCH 74   // weight pitch, halves
#define TROWS  128
#define WT_HALVES (64 * WPITCH)

// Stage 128x64 f32 gmem slab -> half tile (zero-padded).
__device__ __forceinline__ void stage_tile_f32(__half* xs, const float4* src4,
                                               int n0, int tid) {
#pragma unroll
    for (int it = 0; it < 8; it++) {
        int i = tid + it * 256;                 // float4 index, 2048 total
        int l = i >> 4, kq = i & 15;
        float4 v = make_float4(0.f, 0.f, 0.f, 0.f);
        if (n0 + l < N_NODES) v = src4[i];
        __half2 h01 = __floats2half2_rn(v.x, v.y);
        __half2 h23 = __floats2half2_rn(v.z, v.w);
        uint2 u = make_uint2(*(uint32_t*)&h01, *(uint32_t*)&h23);
        *(uint2*)(xs + l * PITCH + 4 * kq) = u;
    }
}

// Stage 128x64 fp16 slab (8 x uint4 per row) -> half tile, raw copy.
__device__ __forceinline__ void stage_tile_h16(__half* xs, const uint4* src,
                                               int n0, int tid) {
#pragma unroll
    for (int it = 0; it < 4; it++) {
        int i = tid + it * 256;                 // uint4 index, 1024 total
        int l = i >> 3, kq = i & 7;
        uint4 v = make_uint4(0u, 0u, 0u, 0u);
        if (n0 + l < N_NODES) v = src[i];
        *(uint4*)(xs + l * PITCH + 8 * kq) = v;   // 144B pitch: 16B-aligned
    }
}

// Stage 64x64 f32 row-major weights -> transposed half wT[c*74 + k].
// float4 loads (fully coalesced); 4 scalar half stores each.
__device__ __forceinline__ void stage_wT(__half* wt, const float* __restrict__ w,
                                         int tid) {
    const float4* w4 = (const float4*)w;
#pragma unroll
    for (int it = 0; it < 4; it++) {
        int i = tid + it * 256;                 // 1024 float4s
        int k = i >> 4, c0 = (i & 15) * 4;
        float4 v = w4[i];
        wt[(c0 + 0) * WPITCH + k] = __float2half_rn(v.x);
        wt[(c0 + 1) * WPITCH + k] = __float2half_rn(v.y);
        wt[(c0 + 2) * WPITCH + k] = __float2half_rn(v.z);
        wt[(c0 + 3) * WPITCH + k] = __float2half_rn(v.w);
    }
}

// acc += tile[r0..r0+15][0..64) @ W[0..64)[0..64)   (W given as wT[c][k])
__device__ __forceinline__ void mma_sweep(float acc[8][4], const __half* xs,
                                          const __half* wt, int r0, int g, int tig) {
#pragma unroll
    for (int s = 0; s < 4; s++) {
        const int k0 = 16 * s;
        const __half* xr0 = xs + (r0 + g) * PITCH + k0 + 2 * tig;
        const __half* xr8 = xs + (r0 + 8 + g) * PITCH + k0 + 2 * tig;
        uint32_t a0 = *(const uint32_t*)(xr0);
        uint32_t a1 = *(const uint32_t*)(xr8);
        uint32_t a2 = *(const uint32_t*)(xr0 + 8);
        uint32_t a3 = *(const uint32_t*)(xr8 + 8);
#pragma unroll
        for (int t = 0; t < 8; t++) {
            const __half* wc = wt + (8 * t + g) * WPITCH + k0 + 2 * tig;
            uint32_t b0 = *(const uint32_t*)(wc);
            uint32_t b1 = *(const uint32_t*)(wc + 8);
            asm volatile(
                "mma.sync.aligned.m16n8k16.row.col.f32.f16.f16.f32 "
                "{%0,%1,%2,%3}, {%4,%5,%6,%7}, {%8,%9}, {%0,%1,%2,%3};"
                : "+f"(acc[t][0]), "+f"(acc[t][1]), "+f"(acc[t][2]), "+f"(acc[t][3])
                : "r"(a0), "r"(a1), "r"(a2), "r"(a3), "r"(b0), "r"(b1));
        }
    }
}

__device__ __forceinline__ void zero_acc(float acc[8][4]) {
#pragma unroll
    for (int t = 0; t < 8; t++)
#pragma unroll
        for (int p = 0; p < 4; p++) acc[t][p] = 0.f;
}

// relu(acc+bias) -> half tile (warp-own rows), one half2 store per tile-row.
__device__ __forceinline__ void write_h(__half* xs, float acc[8][4],
                                        const float* __restrict__ bias,
                                        int r0, int g, int tig) {
#pragma unroll
    for (int t = 0; t < 8; t++) {
        int c = 8 * t + 2 * tig;
        float b0 = __ldg(bias + c), b1 = __ldg(bias + c + 1);
        __half2 lo = __floats2half2_rn(fmaxf(acc[t][0] + b0, 0.f),
                                       fmaxf(acc[t][1] + b1, 0.f));
        __half2 hi = __floats2half2_rn(fmaxf(acc[t][2] + b0, 0.f),
                                       fmaxf(acc[t][3] + b1, 0.f));
        *(uint32_t*)(xs + (r0 + g) * PITCH + c)     = *(uint32_t*)&lo;
        *(uint32_t*)(xs + (r0 + 8 + g) * PITCH + c) = *(uint32_t*)&hi;
    }
}

// acc+bias -> f32 gmem (guarded), float2 per mma tile-row.
__device__ __forceinline__ void store_out(float* dst, float acc[8][4],
                                          const float* __restrict__ bias,
                                          int n0, int r0, int g, int tig) {
    int nlo = n0 + r0 + g, nhi = nlo + 8;
    bool oklo = nlo < N_NODES, okhi = nhi < N_NODES;
#pragma unroll
    for (int t = 0; t < 8; t++) {
        int c = 8 * t + 2 * tig;
        float b0 = __ldg(bias + c), b1 = __ldg(bias + c + 1);
        if (oklo) {
            float2 v; v.x = acc[t][0] + b0; v.y = acc[t][1] + b1;
            *(float2*)(dst + (size_t)nlo * D + c) = v;
        }
        if (okhi) {
            float2 v; v.x = acc[t][2] + b0; v.y = acc[t][3] + b1;
            *(float2*)(dst + (size_t)nhi * D + c) = v;
        }
    }
}

// acc+bias -> fp16 y buffer (guarded), one half2 (4B) per mma tile-row.
__device__ __forceinline__ void store_out_h(float acc[8][4],
                                            const float* __restrict__ bias,
                                            int n0, int r0, int g, int tig) {
    uint32_t* yh = (uint32_t*)g_yh;   // 32 uints per row
    int nlo = n0 + r0 + g, nhi = nlo + 8;
    bool oklo = nlo < N_NODES, okhi = nhi < N_NODES;
#pragma unroll
    for (int t = 0; t < 8; t++) {
        int c = 8 * t + 2 * tig;
        float b0 = __ldg(bias + c), b1 = __ldg(bias + c + 1);
        if (oklo) {
            __half2 v = __floats2half2_rn(acc[t][0] + b0, acc[t][1] + b1);
            yh[nlo * 32 + (c >> 1)] = *(uint32_t*)&v;
        }
        if (okhi) {
            __half2 v = __floats2half2_rn(acc[t][2] + b0, acc[t][3] + b1);
            yh[nhi * 32 + (c >> 1)] = *(uint32_t*)&v;
        }
    }
}

// ---------------------------------------------------------------------------
// K1: node message MLP  y = relu(x @ W1 + b1) @ W2 + b2   -> fp16 g_yh
// Both weights pre-staged; ONE block sync total. ~36.5KB smem -> 4 CTAs/SM.
// ---------------------------------------------------------------------------
#define K1_SMEM_BYTES ((TROWS * PITCH + 2 * WT_HALVES) * 2)

__global__ __launch_bounds__(256) void k_msg_mlp(
    const float* __restrict__ x,
    const float* __restrict__ w1, const float* __restrict__ b1,
    const float* __restrict__ w2, const float* __restrict__ b2,
    const int* __restrict__ ei32)
{
    extern __shared__ __half smh[];
    __half* xs  = smh;                    // 128*72 half tile (x, then h)
    __half* w1t = xs + TROWS * PITCH;     // 64*74
    __half* w2t = w1t + WT_HALVES;        // 64*74

    const int tid = threadIdx.x;
    const int n0  = blockIdx.x * TROWS;
    const int lane = tid & 31, warp = tid >> 5;
    const int g = lane >> 2, tig = lane & 3;
    const int r0 = warp * 16;

    // Zero this block's g_aggh slice (fp16: 8 x uint4 per row).
    {
        uint4 z = make_uint4(0u, 0u, 0u, 0u);
#pragma unroll
        for (int it = 0; it < 4; it++) {
            int i = n0 * 8 + tid + it * 256;
            if (i < N_NODES * 8) g_aggh[i] = z;
        }
    }
    if (blockIdx.x == 0 && tid == 0) {
        int is64 = 1;
        for (int i = 0; i < 64; i++)
            if (ei32[2 * i + 1] != 0) { is64 = 0; break; }
        g_ei_is64 = is64;
    }

    stage_wT(w1t, w1, tid);
    stage_wT(w2t, w2, tid);
    stage_tile_f32(xs, (const float4*)(x + (size_t)n0 * D), n0, tid);
    __syncthreads();   // the only block-wide sync

    float acc[8][4];
    zero_acc(acc);
    mma_sweep(acc, xs, w1t, r0, g, tig);   // warp-own tile rows only
    __syncwarp();
    write_h(xs, acc, b1, r0, g, tig);      // warp-own tile rows only
    __syncwarp();

    zero_acc(acc);
    mma_sweep(acc, xs, w2t, r0, g, tig);
    store_out_h(acc, b2, n0, r0, g, tig);
}

// ---------------------------------------------------------------------------
// K2: scatter  agg[col] += y[row]  -- all fp16: 8 threads/edge, each does one
// 16B load + one red.global.add.noftz.v4.f16x2 (8 halves per RED).
// ---------------------------------------------------------------------------
__global__ __launch_bounds__(256) void k_scatter(const void* __restrict__ ei_raw)
{
    int tid = blockIdx.x * blockDim.x + threadIdx.x;
    if (tid >= N_EDGES * 8) return;
    int e = tid >> 3;
    int c = tid & 7;

    int row, col;
    if (g_ei_is64) {
        const long long* ei = (const long long*)ei_raw;
        row = (int)ei[e];
        col = (int)ei[N_EDGES + e];
    } else {
        const int* ei = (const int*)ei_raw;
        row = ei[e];
        col = ei[N_EDGES + e];
    }
    if ((unsigned)row >= N_NODES || (unsigned)col >= N_NODES) return;

    uint4 v = g_yh[(size_t)row * 8 + c];
    uint4* q = g_aggh + (size_t)col * 8 + c;
    asm volatile("red.global.add.noftz.v4.f16x2 [%0], {%1,%2,%3,%4};"
                 :: "l"(q), "r"(v.x), "r"(v.y), "r"(v.z), "r"(v.w)
                 : "memory");
}

// ---------------------------------------------------------------------------
// K3: output MLP  out = relu([x,agg] @ W1 + b1) @ W2 + b2     [N,64]
// All 3 weight halves pre-staged; block syncs only around the agg restage.
// ~45.8KB smem -> 4 CTAs/SM.
// ---------------------------------------------------------------------------
#define K3_SMEM_BYTES ((TROWS * PITCH + 3 * WT_HALVES) * 2)

__global__ __launch_bounds__(256) void k_out_mlp(
    const float* __restrict__ x,
    const float* __restrict__ w1, const float* __restrict__ b1,
    const float* __restrict__ w2, const float* __restrict__ b2,
    float* __restrict__ out)
{
    extern __shared__ __half smh[];
    __half* xs   = smh;                    // 128*72 half tile (x, agg, then h)
    __half* w1at = xs + TROWS * PITCH;     // W1 rows 0..63 ^T
    __half* w1bt = w1at + WT_HALVES;       // W1 rows 64..127 ^T
    __half* w2t  = w1bt + WT_HALVES;       // W2 ^T

    const int tid = threadIdx.x;
    const int n0  = blockIdx.x * TROWS;
    const int lane = tid & 31, warp = tid >> 5;
    const int g = lane >> 2, tig = lane & 3;
    const int r0 = warp * 16;

    stage_wT(w1at, w1, tid);
    stage_wT(w1bt, w1 + 64 * 64, tid);
    stage_wT(w2t, w2, tid);
    stage_tile_f32(xs, (const float4*)(x + (size_t)n0 * D), n0, tid);
    __syncthreads();

    float acc[8][4];
    zero_acc(acc);
    mma_sweep(acc, xs, w1at, r0, g, tig);    // k = 0..63 (x)
    __syncthreads();                          // before overwriting tile
    stage_tile_h16(xs, g_aggh + (size_t)n0 * 8, n0, tid);
    __syncthreads();
    mma_sweep(acc, xs, w1bt, r0, g, tig);    // k = 64..127 (agg)
    __syncwarp();
    write_h(xs, acc, b1, r0, g, tig);
    __syncwarp();

    zero_acc(acc);
    mma_sweep(acc, xs, w2t, r0, g, tig);
    store_out(out, acc, b2, n0, r0, g, tig);
}

// ---------------------------------------------------------------------------
// Launch. Inputs: 0 x, 1 edge_index, 2 batch, 3..6 msg mlp, 7..10 out mlp
// ---------------------------------------------------------------------------
extern "C" void kernel_launch(void* const* d_in, const int* in_sizes, int n_in,
                              void* d_out, int out_size)
{
    const float* x      = (const float*)d_in[0];
    const void*  ei     = d_in[1];
    const float* msg_w1 = (const float*)d_in[3];
    const float* msg_b1 = (const float*)d_in[4];
    const float* msg_w2 = (const float*)d_in[5];
    const float* msg_b2 = (const float*)d_in[6];
    const float* out_w1 = (const float*)d_in[7];
    const float* out_b1 = (const float*)d_in[8];
    const float* out_w2 = (const float*)d_in[9];
    const float* out_b2 = (const float*)d_in[10];
    float*       out    = (float*)d_out;

    cudaFuncSetAttribute(k_msg_mlp, cudaFuncAttributeMaxDynamicSharedMemorySize, K1_SMEM_BYTES);
    cudaFuncSetAttribute(k_out_mlp, cudaFuncAttributeMaxDynamicSharedMemorySize, K3_SMEM_BYTES);

    const int nodeBlocks = (N_NODES + TROWS - 1) / TROWS;   // 782

    k_msg_mlp<<<nodeBlocks, 256, K1_SMEM_BYTES>>>(x, msg_w1, msg_b1, msg_w2, msg_b2,
                                                  (const int*)ei);
    k_scatter<<<(N_EDGES * 8 + 255) / 256, 256>>>(ei);
    k_out_mlp<<<nodeBlocks, 256, K3_SMEM_BYTES>>>(x, out_w1, out_b1, out_w2, out_b2, out);
}

// round 14
// speedup vs baseline: 1.1913x; 1.0034x over previous
#include <cuda_runtime.h>
#include <cuda_fp16.h>
#include <cstdint>

#define N_NODES 100000
#define N_EDGES 1000000
#define D 64

#define PITCH  72   // tile pitch, halves
#define WPITCH 74   // weight pitch, halves (B-frag banks 8t+5g+tig: conflict-free)
#define TROWS  128
#define WT_HALVES (64 * WPITCH)          // 4736 halves
#define WT_U4    (WT_HALVES * 2 / 16)    // 592 uint4 per matrix

// Scratch: device globals (no allocs allowed).
__device__ uint4 g_yh[(size_t)N_NODES * 8];    // message MLP output, fp16
__device__ uint4 g_aggh[(size_t)N_NODES * 8];  // scatter-sum accumulator, fp16
__device__ uint4 g_wt[5 * WT_U4];              // 5 transposed fp16 weight mats
__device__ int   g_ei_is64;                    // 1 if edge_index is int64

// g_wt segments: 0=msg_w1, 1=msg_w2, 2=out_w1[0:64], 3=out_w1[64:128], 4=out_w2

// ---------------------------------------------------------------------------
// K-1: one-time weight transpose f32 [k][c] -> fp16 wT[c*74+k], + dtype detect
// ---------------------------------------------------------------------------
__global__ void k_prep(const float* __restrict__ mw1, const float* __restrict__ mw2,
                       const float* __restrict__ ow1, const float* __restrict__ ow2,
                       const int* __restrict__ ei32)
{
    int gtid = blockIdx.x * blockDim.x + threadIdx.x;
    const float* srcs[5] = { mw1, mw2, ow1, ow1 + 64 * 64, ow2 };
    for (int idx = gtid; idx < 5 * 4096; idx += gridDim.x * blockDim.x) {
        int seg = idx >> 12, within = idx & 4095;
        int k = within >> 6, c = within & 63;
        __half* dst = (__half*)(g_wt + seg * WT_U4);
        dst[c * WPITCH + k] = __float2half_rn(srcs[seg][within]);
    }
    if (gtid == 0) {
        int is64 = 1;
        for (int i = 0; i < 64; i++)
            if (ei32[2 * i + 1] != 0) { is64 = 0; break; }
        g_ei_is64 = is64;
    }
}

// ---------------------------------------------------------------------------
// fp16 tensor-core MLP building blocks (m16n8k16, f32 accum).
// CTA = 256 threads (8 warps); tile = 128 rows x 64 cols half, pitch 72.
// Warp w owns rows [16w,16w+16); weights wT[c*74+k] in smem (raw-copied).
// ---------------------------------------------------------------------------

// Raw-copy one transposed weight matrix (592 uint4) into smem.
__device__ __forceinline__ void copy_w(__half* wt, const uint4* src, int tid) {
#pragma unroll
    for (int it = 0; it < 3; it++) {
        int i = tid + it * 256;
        if (i < WT_U4) ((uint4*)wt)[i] = src[i];
    }
}

// Stage 128x64 f32 gmem slab -> half tile (zero-padded).
__device__ __forceinline__ void stage_tile_f32(__half* xs, const float4* src4,
                                               int n0, int tid) {
#pragma unroll
    for (int it = 0; it < 8; it++) {
        int i = tid + it * 256;
        int l = i >> 4, kq = i & 15;
        float4 v = make_float4(0.f, 0.f, 0.f, 0.f);
        if (n0 + l < N_NODES) v = src4[i];
        __half2 h01 = __floats2half2_rn(v.x, v.y);
        __half2 h23 = __floats2half2_rn(v.z, v.w);
        uint2 u = make_uint2(*(uint32_t*)&h01, *(uint32_t*)&h23);
        *(uint2*)(xs + l * PITCH + 4 * kq) = u;
    }
}

// Stage 128x64 fp16 slab -> half tile, raw copy (zero-padded).
__device__ __forceinline__ void stage_tile_h16(__half* xs, const uint4* src,
                                               int n0, int tid) {
#pragma unroll
    for (int it = 0; it < 4; it++) {
        int i = tid + it * 256;
        int l = i >> 3, kq = i & 7;
        uint4 v = make_uint4(0u, 0u, 0u, 0u);
        if (n0 + l < N_NODES) v = src[i];
        *(uint4*)(xs + l * PITCH + 8 * kq) = v;
    }
}

// acc += tile[r0..r0+15][0..64) @ W (wT[c][k])
__device__ __forceinline__ void mma_sweep(float acc[8][4], const __half* xs,
                                          const __half* wt, int r0, int g, int tig) {
#pragma unroll
    for (int s = 0; s < 4; s++) {
        const int k0 = 16 * s;
        const __half* xr0 = xs + (r0 + g) * PITCH + k0 + 2 * tig;
        const __half* xr8 = xs + (r0 + 8 + g) * PITCH + k0 + 2 * tig;
        uint32_t a0 = *(const uint32_t*)(xr0);
        uint32_t a1 = *(const uint32_t*)(xr8);
        uint32_t a2 = *(const uint32_t*)(xr0 + 8);
        uint32_t a3 = *(const uint32_t*)(xr8 + 8);
#pragma unroll
        for (int t = 0; t < 8; t++) {
            const __half* wc = wt + (8 * t + g) * WPITCH + k0 + 2 * tig;
            uint32_t b0 = *(const uint32_t*)(wc);
            uint32_t b1 = *(const uint32_t*)(wc + 8);
            asm volatile(
                "mma.sync.aligned.m16n8k16.row.col.f32.f16.f16.f32 "
                "{%0,%1,%2,%3}, {%4,%5,%6,%7}, {%8,%9}, {%0,%1,%2,%3};"
                : "+f"(acc[t][0]), "+f"(acc[t][1]), "+f"(acc[t][2]), "+f"(acc[t][3])
                : "r"(a0), "r"(a1), "r"(a2), "r"(a3), "r"(b0), "r"(b1));
        }
    }
}

__device__ __forceinline__ void zero_acc(float acc[8][4]) {
#pragma unroll
    for (int t = 0; t < 8; t++)
#pragma unroll
        for (int p = 0; p < 4; p++) acc[t][p] = 0.f;
}

// relu(acc+bias) -> half tile (warp-own rows).
__device__ __forceinline__ void write_h(__half* xs, float acc[8][4],
                                        const float* __restrict__ bias,
                                        int r0, int g, int tig) {
#pragma unroll
    for (int t = 0; t < 8; t++) {
        int c = 8 * t + 2 * tig;
        float b0 = __ldg(bias + c), b1 = __ldg(bias + c + 1);
        __half2 lo = __floats2half2_rn(fmaxf(acc[t][0] + b0, 0.f),
                                       fmaxf(acc[t][1] + b1, 0.f));
        __half2 hi = __floats2half2_rn(fmaxf(acc[t][2] + b0, 0.f),
                                       fmaxf(acc[t][3] + b1, 0.f));
        *(uint32_t*)(xs + (r0 + g) * PITCH + c)     = *(uint32_t*)&lo;
        *(uint32_t*)(xs + (r0 + 8 + g) * PITCH + c) = *(uint32_t*)&hi;
    }
}

// acc+bias -> f32 gmem (guarded).
__device__ __forceinline__ void store_out(float* dst, float acc[8][4],
                                          const float* __restrict__ bias,
                                          int n0, int r0, int g, int tig) {
    int nlo = n0 + r0 + g, nhi = nlo + 8;
    bool oklo = nlo < N_NODES, okhi = nhi < N_NODES;
#pragma unroll
    for (int t = 0; t < 8; t++) {
        int c = 8 * t + 2 * tig;
        float b0 = __ldg(bias + c), b1 = __ldg(bias + c + 1);
        if (oklo) {
            float2 v; v.x = acc[t][0] + b0; v.y = acc[t][1] + b1;
            *(float2*)(dst + (size_t)nlo * D + c) = v;
        }
        if (okhi) {
            float2 v; v.x = acc[t][2] + b0; v.y = acc[t][3] + b1;
            *(float2*)(dst + (size_t)nhi * D + c) = v;
        }
    }
}

// acc+bias -> fp16 y buffer (guarded).
__device__ __forceinline__ void store_out_h(float acc[8][4],
                                            const float* __restrict__ bias,
                                            int n0, int r0, int g, int tig) {
    uint32_t* yh = (uint32_t*)g_yh;
    int nlo = n0 + r0 + g, nhi = nlo + 8;
    bool oklo = nlo < N_NODES, okhi = nhi < N_NODES;
#pragma unroll
    for (int t = 0; t < 8; t++) {
        int c = 8 * t + 2 * tig;
        float b0 = __ldg(bias + c), b1 = __ldg(bias + c + 1);
        if (oklo) {
            __half2 v = __floats2half2_rn(acc[t][0] + b0, acc[t][1] + b1);
            yh[nlo * 32 + (c >> 1)] = *(uint32_t*)&v;
        }
        if (okhi) {
            __half2 v = __floats2half2_rn(acc[t][2] + b0, acc[t][3] + b1);
            yh[nhi * 32 + (c >> 1)] = *(uint32_t*)&v;
        }
    }
}

// ---------------------------------------------------------------------------
// K1: node message MLP  y = relu(x @ W1 + b1) @ W2 + b2   -> fp16 g_yh
// Weights raw-copied from g_wt; ONE block sync. ~36.5KB smem.
// ---------------------------------------------------------------------------
#define K1_SMEM_BYTES ((TROWS * PITCH + 2 * WT_HALVES) * 2)

__global__ __launch_bounds__(256) void k_msg_mlp(
    const float* __restrict__ x,
    const float* __restrict__ b1, const float* __restrict__ b2)
{
    extern __shared__ __half smh[];
    __half* xs  = smh;                    // 128*72 half tile (x, then h)
    __half* w1t = xs + TROWS * PITCH;
    __half* w2t = w1t + WT_HALVES;

    const int tid = threadIdx.x;
    const int n0  = blockIdx.x * TROWS;
    const int lane = tid & 31, warp = tid >> 5;
    const int g = lane >> 2, tig = lane & 3;
    const int r0 = warp * 16;

    // Zero this block's g_aggh slice.
    {
        uint4 z = make_uint4(0u, 0u, 0u, 0u);
#pragma unroll
        for (int it = 0; it < 4; it++) {
            int i = n0 * 8 + tid + it * 256;
            if (i < N_NODES * 8) g_aggh[i] = z;
        }
    }

    copy_w(w1t, g_wt + 0 * WT_U4, tid);
    copy_w(w2t, g_wt + 1 * WT_U4, tid);
    stage_tile_f32(xs, (const float4*)(x + (size_t)n0 * D), n0, tid);
    __syncthreads();   // the only block-wide sync

    float acc[8][4];
    zero_acc(acc);
    mma_sweep(acc, xs, w1t, r0, g, tig);
    __syncwarp();
    write_h(xs, acc, b1, r0, g, tig);
    __syncwarp();

    zero_acc(acc);
    mma_sweep(acc, xs, w2t, r0, g, tig);
    store_out_h(acc, b2, n0, r0, g, tig);
}

// ---------------------------------------------------------------------------
// K2: scatter  agg[col] += y[row]  -- fp16: 8 threads/edge, one
// red.global.add.noftz.v4.f16x2 (8 halves) each.
// ---------------------------------------------------------------------------
__global__ __launch_bounds__(256) void k_scatter(const void* __restrict__ ei_raw)
{
    int tid = blockIdx.x * blockDim.x + threadIdx.x;
    if (tid >= N_EDGES * 8) return;
    int e = tid >> 3;
    int c = tid & 7;

    int row, col;
    if (g_ei_is64) {
        const long long* ei = (const long long*)ei_raw;
        row = (int)ei[e];
        col = (int)ei[N_EDGES + e];
    } else {
        const int* ei = (const int*)ei_raw;
        row = ei[e];
        col = ei[N_EDGES + e];
    }
    if ((unsigned)row >= N_NODES || (unsigned)col >= N_NODES) return;

    uint4 v = g_yh[(size_t)row * 8 + c];
    uint4* q = g_aggh + (size_t)col * 8 + c;
    asm volatile("red.global.add.noftz.v4.f16x2 [%0], {%1,%2,%3,%4};"
                 :: "l"(q), "r"(v.x), "r"(v.y), "r"(v.z), "r"(v.w)
                 : "memory");
}

// ---------------------------------------------------------------------------
// K3: output MLP  out = relu([x,agg] @ W1 + b1) @ W2 + b2     [N,64]
// Separate x and agg tiles staged before the single sync -> zero mid-kernel
// block syncs (each warp only touches its own 16 rows). ~63.8KB smem.
// ---------------------------------------------------------------------------
#define K3_SMEM_BYTES ((2 * TROWS * PITCH + 3 * WT_HALVES) * 2)

__global__ __launch_bounds__(256) void k_out_mlp(
    const float* __restrict__ x,
    const float* __restrict__ b1, const float* __restrict__ b2,
    float* __restrict__ out)
{
    extern __shared__ __half smh[];
    __half* xs   = smh;                    // x tile (then h)
    __half* as   = xs + TROWS * PITCH;     // agg tile
    __half* w1at = as + TROWS * PITCH;
    __half* w1bt = w1at + WT_HALVES;
    __half* w2t  = w1bt + WT_HALVES;

    const int tid = threadIdx.x;
    const int n0  = blockIdx.x * TROWS;
    const int lane = tid & 31, warp = tid >> 5;
    const int g = lane >> 2, tig = lane & 3;
    const int r0 = warp * 16;

    copy_w(w1at, g_wt + 2 * WT_U4, tid);
    copy_w(w1bt, g_wt + 3 * WT_U4, tid);
    copy_w(w2t,  g_wt + 4 * WT_U4, tid);
    stage_tile_f32(xs, (const float4*)(x + (size_t)n0 * D), n0, tid);
    stage_tile_h16(as, g_aggh + (size_t)n0 * 8, n0, tid);
    __syncthreads();   // the only block-wide sync

    float acc[8][4];
    zero_acc(acc);
    mma_sweep(acc, xs, w1at, r0, g, tig);    // k = 0..63 (x)
    mma_sweep(acc, as, w1bt, r0, g, tig);    // k = 64..127 (agg)
    __syncwarp();
    write_h(xs, acc, b1, r0, g, tig);        // warp-own rows only
    __syncwarp();

    zero_acc(acc);
    mma_sweep(acc, xs, w2t, r0, g, tig);
    store_out(out, acc, b2, n0, r0, g, tig);
}

// ---------------------------------------------------------------------------
// Launch. Inputs: 0 x, 1 edge_index, 2 batch, 3..6 msg mlp, 7..10 out mlp
// ---------------------------------------------------------------------------
extern "C" void kernel_launch(void* const* d_in, const int* in_sizes, int n_in,
                              void* d_out, int out_size)
{
    const float* x      = (const float*)d_in[0];
    const void*  ei     = d_in[1];
    const float* msg_w1 = (const float*)d_in[3];
    const float* msg_b1 = (const float*)d_in[4];
    const float* msg_w2 = (const float*)d_in[5];
    const float* msg_b2 = (const float*)d_in[6];
    const float* out_w1 = (const float*)d_in[7];
    const float* out_b1 = (const float*)d_in[8];
    const float* out_w2 = (const float*)d_in[9];
    const float* out_b2 = (const float*)d_in[10];
    float*       out    = (float*)d_out;

    cudaFuncSetAttribute(k_msg_mlp, cudaFuncAttributeMaxDynamicSharedMemorySize, K1_SMEM_BYTES);
    cudaFuncSetAttribute(k_out_mlp, cudaFuncAttributeMaxDynamicSharedMemorySize, K3_SMEM_BYTES);

    const int nodeBlocks = (N_NODES + TROWS - 1) / TROWS;   // 782

    k_prep<<<20, 256>>>(msg_w1, msg_w2, out_w1, out_w2, (const int*)ei);
    k_msg_mlp<<<nodeBlocks, 256, K1_SMEM_BYTES>>>(x, msg_b1, msg_b2);
    k_scatter<<<(N_EDGES * 8 + 255) / 256, 256>>>(ei);
    k_out_mlp<<<nodeBlocks, 256, K3_SMEM_BYTES>>>(x, out_b1, out_b2, out);
}

// round 15
// speedup vs baseline: 1.3390x; 1.1240x over previous
#include <cuda_runtime.h>
#include <cuda_fp16.h>
#include <cstdint>

#define N_NODES 100000
#define N_EDGES 1000000
#define D 64

#define PITCH  72   // tile pitch, halves (144B rows: LDSM conflict-free)
#define WPITCH 72   // weight pitch, halves (LDSM conflict-free at 16B grain)
#define TROWS  128
#define WT_HALVES (64 * WPITCH)          // 4608 halves
#define WT_U4    (WT_HALVES * 2 / 16)    // 576 uint4 per matrix

// Scratch: device globals (no allocs allowed).
__device__ uint4 g_yh[(size_t)N_NODES * 8];    // message MLP output, fp16
__device__ uint4 g_aggh[(size_t)N_NODES * 8];  // scatter-sum accumulator, fp16
__device__ uint4 g_wt[5 * WT_U4];              // 5 transposed fp16 weight mats
__device__ int   g_ei_is64;                    // 1 if edge_index is int64

// g_wt segments: 0=msg_w1, 1=msg_w2, 2=out_w1[0:64], 3=out_w1[64:128], 4=out_w2

__device__ __forceinline__ uint32_t s2u(const void* p) {
    return (uint32_t)__cvta_generic_to_shared(p);
}

// ---------------------------------------------------------------------------
// K-1: one-time weight transpose f32 [k][c] -> fp16 wT[c*72+k], + dtype detect
// ---------------------------------------------------------------------------
__global__ void k_prep(const float* __restrict__ mw1, const float* __restrict__ mw2,
                       const float* __restrict__ ow1, const float* __restrict__ ow2,
                       const int* __restrict__ ei32)
{
    int gtid = blockIdx.x * blockDim.x + threadIdx.x;
    const float* srcs[5] = { mw1, mw2, ow1, ow1 + 64 * 64, ow2 };
    for (int idx = gtid; idx < 5 * 4096; idx += gridDim.x * blockDim.x) {
        int seg = idx >> 12, within = idx & 4095;
        int k = within >> 6, c = within & 63;
        __half* dst = (__half*)(g_wt + seg * WT_U4);
        dst[c * WPITCH + k] = __float2half_rn(srcs[seg][within]);
    }
    if (gtid == 0) {
        int is64 = 1;
        for (int i = 0; i < 64; i++)
            if (ei32[2 * i + 1] != 0) { is64 = 0; break; }
        g_ei_is64 = is64;
    }
}

// ---------------------------------------------------------------------------
// fp16 tensor-core MLP building blocks (m16n8k16, f32 accum, ldmatrix feed).
// CTA = 256 threads (8 warps); tile = 128 rows x 64 cols half, pitch 72.
// Warp w owns rows [16w,16w+16); 8 mma tiles per warp; k-loop 4.
// ---------------------------------------------------------------------------

// Raw-copy one transposed weight matrix (576 uint4) into smem.
__device__ __forceinline__ void copy_w(__half* wt, const uint4* src, int tid) {
#pragma unroll
    for (int it = 0; it < 3; it++) {
        int i = tid + it * 256;
        if (i < WT_U4) ((uint4*)wt)[i] = src[i];
    }
}

// Stage 128x64 f32 gmem slab -> half tile (zero-padded).
__device__ __forceinline__ void stage_tile_f32(__half* xs, const float4* src4,
                                               int n0, int tid) {
#pragma unroll
    for (int it = 0; it < 8; it++) {
        int i = tid + it * 256;
        int l = i >> 4, kq = i & 15;
        float4 v = make_float4(0.f, 0.f, 0.f, 0.f);
        if (n0 + l < N_NODES) v = src4[i];
        __half2 h01 = __floats2half2_rn(v.x, v.y);
        __half2 h23 = __floats2half2_rn(v.z, v.w);
        uint2 u = make_uint2(*(uint32_t*)&h01, *(uint32_t*)&h23);
        *(uint2*)(xs + l * PITCH + 4 * kq) = u;
    }
}

// Stage 128x64 fp16 slab -> half tile, raw copy (zero-padded).
__device__ __forceinline__ void stage_tile_h16(__half* xs, const uint4* src,
                                               int n0, int tid) {
#pragma unroll
    for (int it = 0; it < 4; it++) {
        int i = tid + it * 256;
        int l = i >> 3, kq = i & 7;
        uint4 v = make_uint4(0u, 0u, 0u, 0u);
        if (n0 + l < N_NODES) v = src[i];
        *(uint4*)(xs + l * PITCH + 8 * kq) = v;
    }
}

// acc += tile[r0..r0+15][0..64) @ W (wT[c][k]), ldmatrix-fed.
// A addresses (lane i): row r0 + (i&7) + 8*((i>>3)&1), k-off 8*(i>>4).
// B addresses (lane i): col (i&7) + 8*(i>>4), k-off 8*((i>>3)&1).
__device__ __forceinline__ void mma_sweep(float acc[8][4], const __half* xs,
                                          const __half* wt, int r0, int lane) {
    const int arow = r0 + (lane & 7) + ((lane >> 3) & 1) * 8;
    const int akof = (lane >> 4) * 8;
    uint32_t abase = s2u(xs + arow * PITCH + akof);
    const int bcol = (lane & 7) + (lane >> 4) * 8;
    const int bkof = ((lane >> 3) & 1) * 8;
    uint32_t bbase = s2u(wt + bcol * WPITCH + bkof);

#pragma unroll
    for (int s = 0; s < 4; s++) {
        uint32_t a0, a1, a2, a3;
        asm volatile(
            "ldmatrix.sync.aligned.m8n8.x4.shared.b16 {%0,%1,%2,%3}, [%4];"
            : "=r"(a0), "=r"(a1), "=r"(a2), "=r"(a3)
            : "r"(abase + 32 * s));
#pragma unroll
        for (int tp = 0; tp < 4; tp++) {
            uint32_t b0, b1, b2, b3;
            asm volatile(
                "ldmatrix.sync.aligned.m8n8.x4.shared.b16 {%0,%1,%2,%3}, [%4];"
                : "=r"(b0), "=r"(b1), "=r"(b2), "=r"(b3)
                : "r"(bbase + tp * (16 * WPITCH * 2) + 32 * s));
            float* c0 = acc[2 * tp];
            float* c1 = acc[2 * tp + 1];
            asm volatile(
                "mma.sync.aligned.m16n8k16.row.col.f32.f16.f16.f32 "
                "{%0,%1,%2,%3}, {%4,%5,%6,%7}, {%8,%9}, {%0,%1,%2,%3};"
                : "+f"(c0[0]), "+f"(c0[1]), "+f"(c0[2]), "+f"(c0[3])
                : "r"(a0), "r"(a1), "r"(a2), "r"(a3), "r"(b0), "r"(b1));
            asm volatile(
                "mma.sync.aligned.m16n8k16.row.col.f32.f16.f16.f32 "
                "{%0,%1,%2,%3}, {%4,%5,%6,%7}, {%8,%9}, {%0,%1,%2,%3};"
                : "+f"(c1[0]), "+f"(c1[1]), "+f"(c1[2]), "+f"(c1[3])
                : "r"(a0), "r"(a1), "r"(a2), "r"(a3), "r"(b2), "r"(b3));
        }
    }
}

__device__ __forceinline__ void zero_acc(float acc[8][4]) {
#pragma unroll
    for (int t = 0; t < 8; t++)
#pragma unroll
        for (int p = 0; p < 4; p++) acc[t][p] = 0.f;
}

// relu(acc+bias) -> half tile (warp-own rows).
__device__ __forceinline__ void write_h(__half* xs, float acc[8][4],
                                        const float* __restrict__ bias,
                                        int r0, int g, int tig) {
#pragma unroll
    for (int t = 0; t < 8; t++) {
        int c = 8 * t + 2 * tig;
        float b0 = __ldg(bias + c), b1 = __ldg(bias + c + 1);
        __half2 lo = __floats2half2_rn(fmaxf(acc[t][0] + b0, 0.f),
                                       fmaxf(acc[t][1] + b1, 0.f));
        __half2 hi = __floats2half2_rn(fmaxf(acc[t][2] + b0, 0.f),
                                       fmaxf(acc[t][3] + b1, 0.f));
        *(uint32_t*)(xs + (r0 + g) * PITCH + c)     = *(uint32_t*)&lo;
        *(uint32_t*)(xs + (r0 + 8 + g) * PITCH + c) = *(uint32_t*)&hi;
    }
}

// acc+bias -> f32 gmem (guarded).
__device__ __forceinline__ void store_out(float* dst, float acc[8][4],
                                          const float* __restrict__ bias,
                                          int n0, int r0, int g, int tig) {
    int nlo = n0 + r0 + g, nhi = nlo + 8;
    bool oklo = nlo < N_NODES, okhi = nhi < N_NODES;
#pragma unroll
    for (int t = 0; t < 8; t++) {
        int c = 8 * t + 2 * tig;
        float b0 = __ldg(bias + c), b1 = __ldg(bias + c + 1);
        if (oklo) {
            float2 v; v.x = acc[t][0] + b0; v.y = acc[t][1] + b1;
            *(float2*)(dst + (size_t)nlo * D + c) = v;
        }
        if (okhi) {
            float2 v; v.x = acc[t][2] + b0; v.y = acc[t][3] + b1;
            *(float2*)(dst + (size_t)nhi * D + c) = v;
        }
    }
}

// acc+bias -> fp16 y buffer (guarded).
__device__ __forceinline__ void store_out_h(float acc[8][4],
                                            const float* __restrict__ bias,
                                            int n0, int r0, int g, int tig) {
    uint32_t* yh = (uint32_t*)g_yh;
    int nlo = n0 + r0 + g, nhi = nlo + 8;
    bool oklo = nlo < N_NODES, okhi = nhi < N_NODES;
#pragma unroll
    for (int t = 0; t < 8; t++) {
        int c = 8 * t + 2 * tig;
        float b0 = __ldg(bias + c), b1 = __ldg(bias + c + 1);
        if (oklo) {
            __half2 v = __floats2half2_rn(acc[t][0] + b0, acc[t][1] + b1);
            yh[nlo * 32 + (c >> 1)] = *(uint32_t*)&v;
        }
        if (okhi) {
            __half2 v = __floats2half2_rn(acc[t][2] + b0, acc[t][3] + b1);
            yh[nhi * 32 + (c >> 1)] = *(uint32_t*)&v;
        }
    }
}

// ---------------------------------------------------------------------------
// K1: node message MLP  y = relu(x @ W1 + b1) @ W2 + b2   -> fp16 g_yh
// Weights raw-copied from g_wt; ONE block sync. ~36KB smem.
// ---------------------------------------------------------------------------
#define K1_SMEM_BYTES ((TROWS * PITCH + 2 * WT_HALVES) * 2)

__global__ __launch_bounds__(256) void k_msg_mlp(
    const float* __restrict__ x,
    const float* __restrict__ b1, const float* __restrict__ b2)
{
    extern __shared__ __half smh[];
    __half* xs  = smh;                    // 128*72 half tile (x, then h)
    __half* w1t = xs + TROWS * PITCH;
    __half* w2t = w1t + WT_HALVES;

    const int tid = threadIdx.x;
    const int n0  = blockIdx.x * TROWS;
    const int lane = tid & 31, warp = tid >> 5;
    const int g = lane >> 2, tig = lane & 3;
    const int r0 = warp * 16;

    // Zero this block's g_aggh slice.
    {
        uint4 z = make_uint4(0u, 0u, 0u, 0u);
#pragma unroll
        for (int it = 0; it < 4; it++) {
            int i = n0 * 8 + tid + it * 256;
            if (i < N_NODES * 8) g_aggh[i] = z;
        }
    }

    copy_w(w1t, g_wt + 0 * WT_U4, tid);
    copy_w(w2t, g_wt + 1 * WT_U4, tid);
    stage_tile_f32(xs, (const float4*)(x + (size_t)n0 * D), n0, tid);
    __syncthreads();   // the only block-wide sync

    float acc[8][4];
    zero_acc(acc);
    mma_sweep(acc, xs, w1t, r0, lane);
    __syncwarp();
    write_h(xs, acc, b1, r0, g, tig);
    __syncwarp();

    zero_acc(acc);
    mma_sweep(acc, xs, w2t, r0, lane);
    store_out_h(acc, b2, n0, r0, g, tig);
}

// ---------------------------------------------------------------------------
// K2: scatter  agg[col] += y[row]  -- fp16: 8 threads/edge, one
// red.global.add.noftz.v4.f16x2 (8 halves) each.
// ---------------------------------------------------------------------------
__global__ __launch_bounds__(256) void k_scatter(const void* __restrict__ ei_raw)
{
    int tid = blockIdx.x * blockDim.x + threadIdx.x;
    if (tid >= N_EDGES * 8) return;
    int e = tid >> 3;
    int c = tid & 7;

    int row, col;
    if (g_ei_is64) {
        const long long* ei = (const long long*)ei_raw;
        row = (int)ei[e];
        col = (int)ei[N_EDGES + e];
    } else {
        const int* ei = (const int*)ei_raw;
        row = ei[e];
        col = ei[N_EDGES + e];
    }
    if ((unsigned)row >= N_NODES || (unsigned)col >= N_NODES) return;

    uint4 v = g_yh[(size_t)row * 8 + c];
    uint4* q = g_aggh + (size_t)col * 8 + c;
    asm volatile("red.global.add.noftz.v4.f16x2 [%0], {%1,%2,%3,%4};"
                 :: "l"(q), "r"(v.x), "r"(v.y), "r"(v.z), "r"(v.w)
                 : "memory");
}

// ---------------------------------------------------------------------------
// K3: output MLP  out = relu([x,agg] @ W1 + b1) @ W2 + b2     [N,64]
// Separate x and agg tiles; ONE block sync; zero mid-kernel block syncs.
// ~63KB smem.
// ---------------------------------------------------------------------------
#define K3_SMEM_BYTES ((2 * TROWS * PITCH + 3 * WT_HALVES) * 2)

__global__ __launch_bounds__(256) void k_out_mlp(
    const float* __restrict__ x,
    const float* __restrict__ b1, const float* __restrict__ b2,
    float* __restrict__ out)
{
    extern __shared__ __half smh[];
    __half* xs   = smh;                    // x tile (then h)
    __half* as   = xs + TROWS * PITCH;     // agg tile
    __half* w1at = as + TROWS * PITCH;
    __half* w1bt = w1at + WT_HALVES;
    __half* w2t  = w1bt + WT_HALVES;

    const int tid = threadIdx.x;
    const int n0  = blockIdx.x * TROWS;
    const int lane = tid & 31, warp = tid >> 5;
    const int g = lane >> 2, tig = lane & 3;
    const int r0 = warp * 16;

    copy_w(w1at, g_wt + 2 * WT_U4, tid);
    copy_w(w1bt, g_wt + 3 * WT_U4, tid);
    copy_w(w2t,  g_wt + 4 * WT_U4, tid);
    stage_tile_f32(xs, (const float4*)(x + (size_t)n0 * D), n0, tid);
    stage_tile_h16(as, g_aggh + (size_t)n0 * 8, n0, tid);
    __syncthreads();   // the only block-wide sync

    float acc[8][4];
    zero_acc(acc);
    mma_sweep(acc, xs, w1at, r0, lane);    // k = 0..63 (x)
    mma_sweep(acc, as, w1bt, r0, lane);    // k = 64..127 (agg)
    __syncwarp();
    write_h(xs, acc, b1, r0, g, tig);      // warp-own rows only
    __syncwarp();

    zero_acc(acc);
    mma_sweep(acc, xs, w2t, r0, lane);
    store_out(out, acc, b2, n0, r0, g, tig);
}

// ---------------------------------------------------------------------------
// Launch. Inputs: 0 x, 1 edge_index, 2 batch, 3..6 msg mlp, 7..10 out mlp
// ---------------------------------------------------------------------------
extern "C" void kernel_launch(void* const* d_in, const int* in_sizes, int n_in,
                              void* d_out, int out_size)
{
    const float* x      = (const float*)d_in[0];
    const void*  ei     = d_in[1];
    const float* msg_w1 = (const float*)d_in[3];
    const float* msg_b1 = (const float*)d_in[4];
    const float* msg_w2 = (const float*)d_in[5];
    const float* msg_b2 = (const float*)d_in[6];
    const float* out_w1 = (const float*)d_in[7];
    const float* out_b1 = (const float*)d_in[8];
    const float* out_w2 = (const float*)d_in[9];
    const float* out_b2 = (const float*)d_in[10];
    float*       out    = (float*)d_out;

    cudaFuncSetAttribute(k_msg_mlp, cudaFuncAttributeMaxDynamicSharedMemorySize, K1_SMEM_BYTES);
    cudaFuncSetAttribute(k_out_mlp, cudaFuncAttributeMaxDynamicSharedMemorySize, K3_SMEM_BYTES);

    const int nodeBlocks = (N_NODES + TROWS - 1) / TROWS;   // 782

    k_prep<<<20, 256>>>(msg_w1, msg_w2, out_w1, out_w2, (const int*)ei);
    k_msg_mlp<<<nodeBlocks, 256, K1_SMEM_BYTES>>>(x, msg_b1, msg_b2);
    k_scatter<<<(N_EDGES * 8 + 255) / 256, 256>>>(ei);
    k_out_mlp<<<nodeBlocks, 256, K3_SMEM_BYTES>>>(x, out_b1, out_b2, out);
}